// round 12
// baseline (speedup 1.0000x reference)
#include <cuda_runtime.h>
#include <cstdint>

#define P_DIM 1024
#define Q_DIM 1024
#define S_DIM 128
#define B_DIM 8
#define KDIM  (3 * S_DIM)   // 384
#define KC    32            // K-chunk staged in smem
#define TM    64
#define TN    64
#define PR_ROWS 4           // rows per proj CTA

// Device-global scratch (allocation-free rule)
__device__ __align__(16) float g_A[P_DIM * KDIM];  // [p, 3s+j] tf32-rounded
__device__ __align__(16) float g_B[Q_DIM * KDIM];  // [q, 3s+j] tf32-rounded
__device__ __align__(16) float g_u[P_DIM];         // p-only terms (+ rank-0)
__device__ __align__(16) float g_t[Q_DIM];         // q-only terms
__device__ __align__(16) float g_m[P_DIM * Q_DIM]; // leaky(m) adjacency (4MB)

__device__ __forceinline__ float tf32r(float v) {
  uint32_t r;
  asm("cvt.rna.tf32.f32 %0, %1;" : "=r"(r) : "f"(v));
  return __uint_as_float(r);
}

// ---------------------------------------------------------------------------
// Prologue. grid (256, 2), block 512; 4 rows/CTA, one output dot per thread.
// y==0: product side -> g_A rows + g_u.  y==1: person side -> g_B rows + g_t.
// softplus(z) ~= z/2 + ln2 + z^2/8 - z^4/192;  z = pr + pe.
// Cross terms (GEMM, K=3S):  A0=w(pr/4 - pr^3/48), A1=-w pr^2/32, A2=-w pr/48
//                            B0=pe, B1=pe^2, B2=pe^3
// u(p) = sum_s w(pr/2 + pr^2/8 - pr^4/192) + ln2*sum(w);  t(q) analogous.
// ---------------------------------------------------------------------------
__global__ __launch_bounds__(512) void proj_kernel(
    const float* __restrict__ product, const float* __restrict__ person,
    const float* __restrict__ w1, const float* __restrict__ w2) {
  __shared__ float rows[PR_ROWS][S_DIM];
  __shared__ float red[PR_ROWS][4];
  __shared__ float wsum_sm;
  const int tid = threadIdx.x;
  const int s = tid & 127;          // output column
  const int r = tid >> 7;           // row within CTA (0..3)
  const int row0 = blockIdx.x * PR_ROWS;
  const int side = blockIdx.y;
  const float* src = side ? person : product;
  const float* wb = side ? (w1 + S_DIM * S_DIM) : w1;

  if (tid < S_DIM) rows[0][tid] = src[row0 * S_DIM + tid];
  else if (tid < 2 * S_DIM) rows[1][tid - S_DIM] = src[(row0 + 1) * S_DIM + tid - S_DIM];
  else if (tid < 3 * S_DIM) rows[2][tid - 2 * S_DIM] = src[(row0 + 2) * S_DIM + tid - 2 * S_DIM];
  else rows[3][tid - 3 * S_DIM] = src[(row0 + 3) * S_DIM + tid - 3 * S_DIM];

  if (tid < 32) {  // sum(w2) once
    float t = w2[tid] + w2[tid + 32] + w2[tid + 64] + w2[tid + 96];
#pragma unroll
    for (int o = 16; o > 0; o >>= 1) t += __shfl_down_sync(0xffffffffu, t, o);
    if (tid == 0) wsum_sm = t;
  }
  __syncthreads();

  // 128-step dot, 4 accumulators to break the dependent chain.
  float a0 = 0.f, a1 = 0.f, a2 = 0.f, a3 = 0.f;
#pragma unroll 8
  for (int k = 0; k < S_DIM; k += 4) {
    a0 = fmaf(rows[r][k],     wb[k * S_DIM + s],       a0);
    a1 = fmaf(rows[r][k + 1], wb[(k + 1) * S_DIM + s], a1);
    a2 = fmaf(rows[r][k + 2], wb[(k + 2) * S_DIM + s], a2);
    a3 = fmaf(rows[r][k + 3], wb[(k + 3) * S_DIM + s], a3);
  }
  const float v = (a0 + a1) + (a2 + a3);

  const float wv = w2[s];
  const float v2 = v * v, v3 = v2 * v, v4 = v2 * v2;
  float* dst = (side ? g_B : g_A) + (row0 + r) * KDIM + 3 * s;
  if (side == 0) {
    dst[0] = tf32r(wv * (0.25f * v - v3 * (1.f / 48.f)));
    dst[1] = tf32r(-wv * v2 * (1.f / 32.f));
    dst[2] = tf32r(-wv * v * (1.f / 48.f));
  } else {
    dst[0] = tf32r(v);
    dst[1] = tf32r(v2);
    dst[2] = tf32r(v3);
  }

  float rv = wv * (0.5f * v + 0.125f * v2 - v4 * (1.f / 192.f));
#pragma unroll
  for (int o = 16; o > 0; o >>= 1) rv += __shfl_down_sync(0xffffffffu, rv, o);
  if ((tid & 31) == 0) red[r][(tid >> 5) & 3] = rv;
  __syncthreads();

  if (tid < PR_ROWS) {
    const float t = red[tid][0] + red[tid][1] + red[tid][2] + red[tid][3];
    if (side == 0) g_u[row0 + tid] = t + 0.69314718f * wsum_sm;
    else           g_t[row0 + tid] = t;
  }
}

// ---------------------------------------------------------------------------
// GEMM (tf32 mma.sync): m = leaky(u_p + t_q + A.B^T) -> g_m.
// grid (16,16) = 256 CTAs, 256 threads (8 warps). CTA tile 64x64.
// Warp w: rows [16*(w>>1), +16), cols [32*(w&1), +32) -> 4 n-frags.
// ---------------------------------------------------------------------------
#define APAD 36   // row stride (floats) for A/B smem: conflict-free frag reads

__global__ __launch_bounds__(256) void gemm_kernel() {
  __shared__ __align__(16) float A_sm[TM][APAD];
  __shared__ __align__(16) float B_sm[TN][APAD];

  const int tid = threadIdx.x;
  const int warp = tid >> 5;
  const int lane = tid & 31;
  const int gid = lane >> 2;   // 0..7
  const int tig = lane & 3;    // 0..3
  const int p0 = blockIdx.y * TM;
  const int q0 = blockIdx.x * TN;
  const int r0 = (warp >> 1) * 16;   // warp row base within tile
  const int c0 = (warp & 1) * 32;    // warp col base within tile

  float c[4][4];
#pragma unroll
  for (int i = 0; i < 4; ++i)
#pragma unroll
    for (int j = 0; j < 4; ++j) c[i][j] = 0.f;

  const int arow = r0 + gid;

  for (int kc = 0; kc < KDIM; kc += KC) {
    if (kc) __syncthreads();
    // Chunk load: 64 rows x 32 K-floats each side = 512 float4 per matrix.
#pragma unroll
    for (int j = 0; j < 2; ++j) {
      const int idx = tid + j * 256;          // 0..511
      const int r = idx >> 3, c4 = (idx & 7) * 4;
      *reinterpret_cast<float4*>(&A_sm[r][c4]) =
          *reinterpret_cast<const float4*>(&g_A[(p0 + r) * KDIM + kc + c4]);
      *reinterpret_cast<float4*>(&B_sm[r][c4]) =
          *reinterpret_cast<const float4*>(&g_B[(q0 + r) * KDIM + kc + c4]);
    }
    __syncthreads();

#pragma unroll
    for (int ks = 0; ks < KC / 8; ++ks) {
      const int k0 = ks * 8;
      const uint32_t a0 = __float_as_uint(A_sm[arow][k0 + tig]);
      const uint32_t a1 = __float_as_uint(A_sm[arow + 8][k0 + tig]);
      const uint32_t a2 = __float_as_uint(A_sm[arow][k0 + tig + 4]);
      const uint32_t a3 = __float_as_uint(A_sm[arow + 8][k0 + tig + 4]);
#pragma unroll
      for (int nf = 0; nf < 4; ++nf) {
        const int n = c0 + nf * 8 + gid;
        const uint32_t b0 = __float_as_uint(B_sm[n][k0 + tig]);
        const uint32_t b1 = __float_as_uint(B_sm[n][k0 + tig + 4]);
        asm volatile(
            "mma.sync.aligned.m16n8k8.row.col.f32.tf32.tf32.f32 "
            "{%0,%1,%2,%3}, {%4,%5,%6,%7}, {%8,%9}, {%0,%1,%2,%3};"
            : "+f"(c[nf][0]), "+f"(c[nf][1]), "+f"(c[nf][2]), "+f"(c[nf][3])
            : "r"(a0), "r"(a1), "r"(a2), "r"(a3), "r"(b0), "r"(b1));
      }
    }
  }

  // Epilogue: add rank-1 terms, leaky-relu, store m tile (float2, from regs).
  const float u0 = g_u[p0 + arow];
  const float u1 = g_u[p0 + arow + 8];
#pragma unroll
  for (int nf = 0; nf < 4; ++nf) {
    const int col = c0 + nf * 8 + 2 * tig;
    const float2 tv = *reinterpret_cast<const float2*>(&g_t[q0 + col]);
    float m00 = c[nf][0] + u0 + tv.x;
    float m01 = c[nf][1] + u0 + tv.y;
    float m10 = c[nf][2] + u1 + tv.x;
    float m11 = c[nf][3] + u1 + tv.y;
    m00 = m00 >= 0.f ? m00 : 0.1f * m00;
    m01 = m01 >= 0.f ? m01 : 0.1f * m01;
    m10 = m10 >= 0.f ? m10 : 0.1f * m10;
    m11 = m11 >= 0.f ? m11 : 0.1f * m11;
    *reinterpret_cast<float2*>(&g_m[(p0 + arow) * Q_DIM + q0 + col]) =
        make_float2(m00, m01);
    *reinterpret_cast<float2*>(&g_m[(p0 + arow + 8) * Q_DIM + q0 + col]) =
        make_float2(m10, m11);
  }
}

// ---------------------------------------------------------------------------
// Streaming multiply: out[b,p,q] = m[p,q] * x[b,p,q].
// grid 1024 CTAs x 256 threads; one float4 of m per thread, 8 batches.
// Full-chip parallelism (262144 threads), MLP=8, fully coalesced.
// ---------------------------------------------------------------------------
__global__ __launch_bounds__(256) void mul_kernel(
    const float* __restrict__ x, float* __restrict__ out) {
  const int idx = blockIdx.x * 256 + threadIdx.x;  // float4 index in plane
  const float4 a = reinterpret_cast<const float4*>(g_m)[idx];
  const float4* xv = reinterpret_cast<const float4*>(x);
  float4* ov = reinterpret_cast<float4*>(out);
  const int plane4 = (P_DIM * Q_DIM) >> 2;
#pragma unroll
  for (int b = 0; b < B_DIM; ++b) {
    float4 v = xv[b * plane4 + idx];
    v.x *= a.x; v.y *= a.y; v.z *= a.z; v.w *= a.w;
    ov[b * plane4 + idx] = v;
  }
}

extern "C" void kernel_launch(void* const* d_in, const int* in_sizes, int n_in,
                              void* d_out, int out_size) {
  const float* x       = (const float*)d_in[0];  // [8,1024,1024]
  const float* product = (const float*)d_in[1];  // [1024,128]
  const float* person  = (const float*)d_in[2];  // [1024,128]
  const float* w1      = (const float*)d_in[3];  // [256,128]
  const float* w2      = (const float*)d_in[4];  // [128,1]
  float* out = (float*)d_out;                    // [8,1024,1024]

  proj_kernel<<<dim3(P_DIM / PR_ROWS, 2), 512>>>(product, person, w1, w2);
  gemm_kernel<<<dim3(Q_DIM / TN, P_DIM / TM), 256>>>();
  mul_kernel<<<(P_DIM * Q_DIM / 4) / 256, 256>>>(x, out);
}

// round 13
// speedup vs baseline: 1.0182x; 1.0182x over previous
#include <cuda_runtime.h>
#include <cstdint>

#define P_DIM 1024
#define Q_DIM 1024
#define S_DIM 128
#define B_DIM 8
#define KDIM  (3 * S_DIM)   // 384
#define KC    32            // K-chunk staged in smem
#define TM    64
#define TN    64
#define PR_CTA_ROWS 16      // rows per proj CTA
#define PR_THR_ROWS 4       // rows per proj thread

// Device-global scratch (allocation-free rule)
__device__ __align__(16) float g_A[P_DIM * KDIM];  // [p, 3s+j] tf32-rounded
__device__ __align__(16) float g_B[Q_DIM * KDIM];  // [q, 3s+j] tf32-rounded
__device__ __align__(16) float g_u[P_DIM];         // p-only terms (+ rank-0)
__device__ __align__(16) float g_t[Q_DIM];         // q-only terms
__device__ __align__(16) float g_m[P_DIM * Q_DIM]; // leaky(m) adjacency (4MB)

__device__ __forceinline__ float tf32r(float v) {
  uint32_t r;
  asm("cvt.rna.tf32.f32 %0, %1;" : "=r"(r) : "f"(v));
  return __uint_as_float(r);
}

// ---------------------------------------------------------------------------
// Prologue. grid (64, 2), block 512. CTA: 16 rows; thread: 4 rows x 1 col.
// Each wb element is loaded ONCE per thread and reused across 4 rows
// (cuts proj's LDG count 4x vs one-row-per-thread).
// y==0: product side -> g_A rows + g_u.  y==1: person side -> g_B rows + g_t.
// softplus(z) ~= z/2 + ln2 + z^2/8 - z^4/192;  z = pr + pe.
// Cross terms (GEMM, K=3S):  A0=w(pr/4 - pr^3/48), A1=-w pr^2/32, A2=-w pr/48
//                            B0=pe, B1=pe^2, B2=pe^3
// u(p) = sum_s w(pr/2 + pr^2/8 - pr^4/192) + ln2*sum(w);  t(q) analogous.
// ---------------------------------------------------------------------------
__global__ __launch_bounds__(512) void proj_kernel(
    const float* __restrict__ product, const float* __restrict__ person,
    const float* __restrict__ w1, const float* __restrict__ w2) {
  __shared__ float rows[PR_CTA_ROWS][S_DIM];   // 8 KB
  __shared__ float red[PR_CTA_ROWS][4];
  __shared__ float wsum_sm;
  const int tid = threadIdx.x;
  const int s = tid & 127;          // output column
  const int rg = tid >> 7;          // row group (0..3), 4 rows each
  const int row0 = blockIdx.x * PR_CTA_ROWS;
  const int side = blockIdx.y;
  const float* src = side ? person : product;
  const float* wb = side ? (w1 + S_DIM * S_DIM) : w1;

  // Stage 16 input rows (2048 floats; 4 per thread, coalesced).
#pragma unroll
  for (int i = 0; i < 4; ++i) {
    const int idx = tid + i * 512;
    rows[idx >> 7][idx & 127] = src[row0 * S_DIM + idx];
  }
  if (tid < 32) {  // sum(w2) once
    float t = w2[tid] + w2[tid + 32] + w2[tid + 64] + w2[tid + 96];
#pragma unroll
    for (int o = 16; o > 0; o >>= 1) t += __shfl_down_sync(0xffffffffu, t, o);
    if (tid == 0) wsum_sm = t;
  }
  __syncthreads();

  // 4 independent dot products sharing each wb load.
  float acc[PR_THR_ROWS] = {0.f, 0.f, 0.f, 0.f};
  const int rbase = rg * PR_THR_ROWS;
#pragma unroll 4
  for (int k = 0; k < S_DIM; ++k) {
    const float w = wb[k * S_DIM + s];  // coalesced over s, L2-resident
#pragma unroll
    for (int r = 0; r < PR_THR_ROWS; ++r)
      acc[r] = fmaf(rows[rbase + r][k], w, acc[r]);
  }

  const float wv = w2[s];
  float rv[PR_THR_ROWS];
#pragma unroll
  for (int r = 0; r < PR_THR_ROWS; ++r) {
    const float v = acc[r];
    const float v2 = v * v, v3 = v2 * v, v4 = v2 * v2;
    float* dst = (side ? g_B : g_A) + (row0 + rbase + r) * KDIM + 3 * s;
    if (side == 0) {
      dst[0] = tf32r(wv * (0.25f * v - v3 * (1.f / 48.f)));
      dst[1] = tf32r(-wv * v2 * (1.f / 32.f));
      dst[2] = tf32r(-wv * v * (1.f / 48.f));
    } else {
      dst[0] = tf32r(v);
      dst[1] = tf32r(v2);
      dst[2] = tf32r(v3);
    }
    rv[r] = wv * (0.5f * v + 0.125f * v2 - v4 * (1.f / 192.f));
  }

  // Rank-1 reduction over s: warp covers 32 s-values; 4 warps per row group.
#pragma unroll
  for (int r = 0; r < PR_THR_ROWS; ++r) {
    float t = rv[r];
#pragma unroll
    for (int o = 16; o > 0; o >>= 1) t += __shfl_down_sync(0xffffffffu, t, o);
    if ((tid & 31) == 0) red[rbase + r][(tid >> 5) & 3] = t;
  }
  __syncthreads();
  if (tid < PR_CTA_ROWS) {
    const float t = red[tid][0] + red[tid][1] + red[tid][2] + red[tid][3];
    if (side == 0) g_u[row0 + tid] = t + 0.69314718f * wsum_sm;
    else           g_t[row0 + tid] = t;
  }
}

// ---------------------------------------------------------------------------
// GEMM (tf32 mma.sync): m = leaky(u_p + t_q + A.B^T) -> g_m.
// grid (16,16) = 256 CTAs, 256 threads (8 warps). CTA tile 64x64.
// Warp w: rows [16*(w>>1), +16), cols [32*(w&1), +32) -> 4 n-frags.
// ---------------------------------------------------------------------------
#define APAD 36   // row stride (floats) for A/B smem: conflict-free frag reads

__global__ __launch_bounds__(256) void gemm_kernel() {
  __shared__ __align__(16) float A_sm[TM][APAD];
  __shared__ __align__(16) float B_sm[TN][APAD];

  const int tid = threadIdx.x;
  const int warp = tid >> 5;
  const int lane = tid & 31;
  const int gid = lane >> 2;   // 0..7
  const int tig = lane & 3;    // 0..3
  const int p0 = blockIdx.y * TM;
  const int q0 = blockIdx.x * TN;
  const int r0 = (warp >> 1) * 16;   // warp row base within tile
  const int c0 = (warp & 1) * 32;    // warp col base within tile

  float c[4][4];
#pragma unroll
  for (int i = 0; i < 4; ++i)
#pragma unroll
    for (int j = 0; j < 4; ++j) c[i][j] = 0.f;

  const int arow = r0 + gid;

  for (int kc = 0; kc < KDIM; kc += KC) {
    if (kc) __syncthreads();
    // Chunk load: 64 rows x 32 K-floats each side = 512 float4 per matrix.
#pragma unroll
    for (int j = 0; j < 2; ++j) {
      const int idx = tid + j * 256;          // 0..511
      const int r = idx >> 3, c4 = (idx & 7) * 4;
      *reinterpret_cast<float4*>(&A_sm[r][c4]) =
          *reinterpret_cast<const float4*>(&g_A[(p0 + r) * KDIM + kc + c4]);
      *reinterpret_cast<float4*>(&B_sm[r][c4]) =
          *reinterpret_cast<const float4*>(&g_B[(q0 + r) * KDIM + kc + c4]);
    }
    __syncthreads();

#pragma unroll
    for (int ks = 0; ks < KC / 8; ++ks) {
      const int k0 = ks * 8;
      const uint32_t a0 = __float_as_uint(A_sm[arow][k0 + tig]);
      const uint32_t a1 = __float_as_uint(A_sm[arow + 8][k0 + tig]);
      const uint32_t a2 = __float_as_uint(A_sm[arow][k0 + tig + 4]);
      const uint32_t a3 = __float_as_uint(A_sm[arow + 8][k0 + tig + 4]);
#pragma unroll
      for (int nf = 0; nf < 4; ++nf) {
        const int n = c0 + nf * 8 + gid;
        const uint32_t b0 = __float_as_uint(B_sm[n][k0 + tig]);
        const uint32_t b1 = __float_as_uint(B_sm[n][k0 + tig + 4]);
        asm volatile(
            "mma.sync.aligned.m16n8k8.row.col.f32.tf32.tf32.f32 "
            "{%0,%1,%2,%3}, {%4,%5,%6,%7}, {%8,%9}, {%0,%1,%2,%3};"
            : "+f"(c[nf][0]), "+f"(c[nf][1]), "+f"(c[nf][2]), "+f"(c[nf][3])
            : "r"(a0), "r"(a1), "r"(a2), "r"(a3), "r"(b0), "r"(b1));
      }
    }
  }

  // Epilogue: add rank-1 terms, leaky-relu, store m tile (float2, from regs).
  const float u0 = g_u[p0 + arow];
  const float u1 = g_u[p0 + arow + 8];
#pragma unroll
  for (int nf = 0; nf < 4; ++nf) {
    const int col = c0 + nf * 8 + 2 * tig;
    const float2 tv = *reinterpret_cast<const float2*>(&g_t[q0 + col]);
    float m00 = c[nf][0] + u0 + tv.x;
    float m01 = c[nf][1] + u0 + tv.y;
    float m10 = c[nf][2] + u1 + tv.x;
    float m11 = c[nf][3] + u1 + tv.y;
    m00 = m00 >= 0.f ? m00 : 0.1f * m00;
    m01 = m01 >= 0.f ? m01 : 0.1f * m01;
    m10 = m10 >= 0.f ? m10 : 0.1f * m10;
    m11 = m11 >= 0.f ? m11 : 0.1f * m11;
    *reinterpret_cast<float2*>(&g_m[(p0 + arow) * Q_DIM + q0 + col]) =
        make_float2(m00, m01);
    *reinterpret_cast<float2*>(&g_m[(p0 + arow + 8) * Q_DIM + q0 + col]) =
        make_float2(m10, m11);
  }
}

// ---------------------------------------------------------------------------
// Streaming multiply: out[b,p,q] = m[p,q] * x[b,p,q].
// grid 1024 CTAs x 256 threads; one float4 of m per thread, 8 batches.
// Full-chip parallelism (262144 threads), MLP=8, fully coalesced.
// ---------------------------------------------------------------------------
__global__ __launch_bounds__(256) void mul_kernel(
    const float* __restrict__ x, float* __restrict__ out) {
  const int idx = blockIdx.x * 256 + threadIdx.x;  // float4 index in plane
  const float4 a = reinterpret_cast<const float4*>(g_m)[idx];
  const float4* xv = reinterpret_cast<const float4*>(x);
  float4* ov = reinterpret_cast<float4*>(out);
  const int plane4 = (P_DIM * Q_DIM) >> 2;
#pragma unroll
  for (int b = 0; b < B_DIM; ++b) {
    float4 v = xv[b * plane4 + idx];
    v.x *= a.x; v.y *= a.y; v.z *= a.z; v.w *= a.w;
    ov[b * plane4 + idx] = v;
  }
}

extern "C" void kernel_launch(void* const* d_in, const int* in_sizes, int n_in,
                              void* d_out, int out_size) {
  const float* x       = (const float*)d_in[0];  // [8,1024,1024]
  const float* product = (const float*)d_in[1];  // [1024,128]
  const float* person  = (const float*)d_in[2];  // [1024,128]
  const float* w1      = (const float*)d_in[3];  // [256,128]
  const float* w2      = (const float*)d_in[4];  // [128,1]
  float* out = (float*)d_out;                    // [8,1024,1024]

  proj_kernel<<<dim3(P_DIM / PR_CTA_ROWS, 2), 512>>>(product, person, w1, w2);
  gemm_kernel<<<dim3(Q_DIM / TN, P_DIM / TM), 256>>>();
  mul_kernel<<<(P_DIM * Q_DIM / 4) / 256, 256>>>(x, out);
}

// round 14
// speedup vs baseline: 1.1477x; 1.1272x over previous
#include <cuda_runtime.h>
#include <cstdint>

#define P_DIM 1024
#define Q_DIM 1024
#define S_DIM 128
#define B_DIM 8
#define KDIM  (3 * S_DIM)   // 384
#define KC    32            // K-chunk staged in smem (gemm)
#define TM    64
#define TN    64
#define PR_CTA_ROWS 16      // rows per proj CTA

// Device-global scratch (allocation-free rule)
__device__ __align__(16) float g_A[P_DIM * KDIM];  // [p, 3s+j] tf32-rounded
__device__ __align__(16) float g_B[Q_DIM * KDIM];  // [q, 3s+j] tf32-rounded
__device__ __align__(16) float g_u[P_DIM];         // p-only terms (+ rank-0)
__device__ __align__(16) float g_t[Q_DIM];         // q-only terms
__device__ __align__(16) float g_m[P_DIM * Q_DIM]; // leaky(m) adjacency (4MB)

__device__ __forceinline__ float tf32r(float v) {
  uint32_t r;
  asm("cvt.rna.tf32.f32 %0, %1;" : "=r"(r) : "f"(v));
  return __uint_as_float(r);
}

// ---------------------------------------------------------------------------
// Prologue, k-split layout. grid (64, 2), block 512. CTA: 16 rows.
// Thread (s = tid&127, kg = tid>>7): owns k-range [32kg, 32kg+32) of column s.
//  1) 32 w-values front-loaded to registers (MLP=32, coalesced over s).
//  2) 16 rows x 32 k FMA; row data via broadcast LDS.128.
//  3) kg-partials reduced through smem; thread (s,kg) emits rows [4kg,4kg+4).
// y==0: product side -> g_A rows + g_u.  y==1: person side -> g_B rows + g_t.
// softplus(z) ~= z/2 + ln2 + z^2/8 - z^4/192;  z = pr + pe.
// Cross terms (GEMM, K=3S):  A0=w(pr/4 - pr^3/48), A1=-w pr^2/32, A2=-w pr/48
//                            B0=pe, B1=pe^2, B2=pe^3
// ---------------------------------------------------------------------------
__global__ __launch_bounds__(512) void proj_kernel(
    const float* __restrict__ product, const float* __restrict__ person,
    const float* __restrict__ w1, const float* __restrict__ w2) {
  __shared__ __align__(16) float rows[PR_CTA_ROWS][S_DIM];  //  8 KB
  __shared__ float red[4][PR_CTA_ROWS][S_DIM];              // 32 KB (kg, r, s)
  __shared__ float red2[PR_CTA_ROWS][4];
  __shared__ float wsum_sm;
  const int tid = threadIdx.x;
  const int s = tid & 127;
  const int kg = tid >> 7;          // 0..3
  const int row0 = blockIdx.x * PR_CTA_ROWS;
  const int side = blockIdx.y;
  const float* src = side ? person : product;
  const float* wb = side ? (w1 + S_DIM * S_DIM) : w1;

  // Stage 16 input rows (2048 floats; coalesced).
#pragma unroll
  for (int i = 0; i < 4; ++i) {
    const int idx = tid + i * 512;
    rows[idx >> 7][idx & 127] = src[row0 * S_DIM + idx];
  }
  if (tid < 32) {  // sum(w2) once
    float t = w2[tid] + w2[tid + 32] + w2[tid + 64] + w2[tid + 96];
#pragma unroll
    for (int o = 16; o > 0; o >>= 1) t += __shfl_down_sync(0xffffffffu, t, o);
    if (tid == 0) wsum_sm = t;
  }

  // Front-load 32 w values (independent, coalesced -> MLP=32).
  float wreg[32];
#pragma unroll
  for (int i = 0; i < 32; ++i) wreg[i] = wb[(kg * 32 + i) * S_DIM + s];
  __syncthreads();

  // 16 rows x 32 k partial dots; row data via broadcast LDS.128.
  float part[PR_CTA_ROWS];
#pragma unroll
  for (int r = 0; r < PR_CTA_ROWS; ++r) {
    float p0 = 0.f, p1 = 0.f, p2 = 0.f, p3 = 0.f;
#pragma unroll
    for (int k4 = 0; k4 < 8; ++k4) {
      const float4 rv4 =
          *reinterpret_cast<const float4*>(&rows[r][kg * 32 + k4 * 4]);
      p0 = fmaf(rv4.x, wreg[k4 * 4], p0);
      p1 = fmaf(rv4.y, wreg[k4 * 4 + 1], p1);
      p2 = fmaf(rv4.z, wreg[k4 * 4 + 2], p2);
      p3 = fmaf(rv4.w, wreg[k4 * 4 + 3], p3);
    }
    part[r] = (p0 + p1) + (p2 + p3);
  }
#pragma unroll
  for (int r = 0; r < PR_CTA_ROWS; ++r) red[kg][r][s] = part[r];
  __syncthreads();

  // Thread (s,kg) finalizes rows [4kg, 4kg+4) at column s.
  const float wv = w2[s];
  const int rbase = kg * 4;
  float rv[4];
#pragma unroll
  for (int i = 0; i < 4; ++i) {
    const int r = rbase + i;
    const float v =
        (red[0][r][s] + red[1][r][s]) + (red[2][r][s] + red[3][r][s]);
    const float v2 = v * v, v3 = v2 * v, v4 = v2 * v2;
    float* dst = (side ? g_B : g_A) + (row0 + r) * KDIM + 3 * s;
    if (side == 0) {
      dst[0] = tf32r(wv * (0.25f * v - v3 * (1.f / 48.f)));
      dst[1] = tf32r(-wv * v2 * (1.f / 32.f));
      dst[2] = tf32r(-wv * v * (1.f / 48.f));
    } else {
      dst[0] = tf32r(v);
      dst[1] = tf32r(v2);
      dst[2] = tf32r(v3);
    }
    rv[i] = wv * (0.5f * v + 0.125f * v2 - v4 * (1.f / 192.f));
  }

  // Rank-1 reduction over s (warp = 32 consecutive s; 4 warps per kg group).
#pragma unroll
  for (int i = 0; i < 4; ++i) {
    float t = rv[i];
#pragma unroll
    for (int o = 16; o > 0; o >>= 1) t += __shfl_down_sync(0xffffffffu, t, o);
    if ((tid & 31) == 0) red2[rbase + i][(tid >> 5) & 3] = t;
  }
  __syncthreads();
  if (tid < PR_CTA_ROWS) {
    const float t = red2[tid][0] + red2[tid][1] + red2[tid][2] + red2[tid][3];
    if (side == 0) g_u[row0 + tid] = t + 0.69314718f * wsum_sm;
    else           g_t[row0 + tid] = t;
  }
}

// ---------------------------------------------------------------------------
// GEMM (tf32 mma.sync): m = leaky(u_p + t_q + A.B^T) -> g_m.
// grid (16,16) = 256 CTAs, 256 threads (8 warps). CTA tile 64x64.
// Warp w: rows [16*(w>>1), +16), cols [32*(w&1), +32) -> 4 n-frags.
// ---------------------------------------------------------------------------
#define APAD 36   // row stride (floats) for A/B smem: conflict-free frag reads

__global__ __launch_bounds__(256) void gemm_kernel() {
  __shared__ __align__(16) float A_sm[TM][APAD];
  __shared__ __align__(16) float B_sm[TN][APAD];

  const int tid = threadIdx.x;
  const int warp = tid >> 5;
  const int lane = tid & 31;
  const int gid = lane >> 2;   // 0..7
  const int tig = lane & 3;    // 0..3
  const int p0 = blockIdx.y * TM;
  const int q0 = blockIdx.x * TN;
  const int r0 = (warp >> 1) * 16;   // warp row base within tile
  const int c0 = (warp & 1) * 32;    // warp col base within tile

  float c[4][4];
#pragma unroll
  for (int i = 0; i < 4; ++i)
#pragma unroll
    for (int j = 0; j < 4; ++j) c[i][j] = 0.f;

  const int arow = r0 + gid;

  for (int kc = 0; kc < KDIM; kc += KC) {
    if (kc) __syncthreads();
    // Chunk load: 64 rows x 32 K-floats each side = 512 float4 per matrix.
#pragma unroll
    for (int j = 0; j < 2; ++j) {
      const int idx = tid + j * 256;          // 0..511
      const int r = idx >> 3, c4 = (idx & 7) * 4;
      *reinterpret_cast<float4*>(&A_sm[r][c4]) =
          *reinterpret_cast<const float4*>(&g_A[(p0 + r) * KDIM + kc + c4]);
      *reinterpret_cast<float4*>(&B_sm[r][c4]) =
          *reinterpret_cast<const float4*>(&g_B[(q0 + r) * KDIM + kc + c4]);
    }
    __syncthreads();

#pragma unroll
    for (int ks = 0; ks < KC / 8; ++ks) {
      const int k0 = ks * 8;
      const uint32_t a0 = __float_as_uint(A_sm[arow][k0 + tig]);
      const uint32_t a1 = __float_as_uint(A_sm[arow + 8][k0 + tig]);
      const uint32_t a2 = __float_as_uint(A_sm[arow][k0 + tig + 4]);
      const uint32_t a3 = __float_as_uint(A_sm[arow + 8][k0 + tig + 4]);
#pragma unroll
      for (int nf = 0; nf < 4; ++nf) {
        const int n = c0 + nf * 8 + gid;
        const uint32_t b0 = __float_as_uint(B_sm[n][k0 + tig]);
        const uint32_t b1 = __float_as_uint(B_sm[n][k0 + tig + 4]);
        asm volatile(
            "mma.sync.aligned.m16n8k8.row.col.f32.tf32.tf32.f32 "
            "{%0,%1,%2,%3}, {%4,%5,%6,%7}, {%8,%9}, {%0,%1,%2,%3};"
            : "+f"(c[nf][0]), "+f"(c[nf][1]), "+f"(c[nf][2]), "+f"(c[nf][3])
            : "r"(a0), "r"(a1), "r"(a2), "r"(a3), "r"(b0), "r"(b1));
      }
    }
  }

  // Epilogue: add rank-1 terms, leaky-relu, store m tile (float2, from regs).
  const float u0 = g_u[p0 + arow];
  const float u1 = g_u[p0 + arow + 8];
#pragma unroll
  for (int nf = 0; nf < 4; ++nf) {
    const int col = c0 + nf * 8 + 2 * tig;
    const float2 tv = *reinterpret_cast<const float2*>(&g_t[q0 + col]);
    float m00 = c[nf][0] + u0 + tv.x;
    float m01 = c[nf][1] + u0 + tv.y;
    float m10 = c[nf][2] + u1 + tv.x;
    float m11 = c[nf][3] + u1 + tv.y;
    m00 = m00 >= 0.f ? m00 : 0.1f * m00;
    m01 = m01 >= 0.f ? m01 : 0.1f * m01;
    m10 = m10 >= 0.f ? m10 : 0.1f * m10;
    m11 = m11 >= 0.f ? m11 : 0.1f * m11;
    *reinterpret_cast<float2*>(&g_m[(p0 + arow) * Q_DIM + q0 + col]) =
        make_float2(m00, m01);
    *reinterpret_cast<float2*>(&g_m[(p0 + arow + 8) * Q_DIM + q0 + col]) =
        make_float2(m10, m11);
  }
}

// ---------------------------------------------------------------------------
// Streaming multiply: out[b,p,q] = m[p,q] * x[b,p,q].
// grid 1024 CTAs x 256 threads; one float4 of m per thread, 8 batches.
// ---------------------------------------------------------------------------
__global__ __launch_bounds__(256) void mul_kernel(
    const float* __restrict__ x, float* __restrict__ out) {
  const int idx = blockIdx.x * 256 + threadIdx.x;  // float4 index in plane
  const float4 a = reinterpret_cast<const float4*>(g_m)[idx];
  const float4* xv = reinterpret_cast<const float4*>(x);
  float4* ov = reinterpret_cast<float4*>(out);
  const int plane4 = (P_DIM * Q_DIM) >> 2;
#pragma unroll
  for (int b = 0; b < B_DIM; ++b) {
    float4 v = xv[b * plane4 + idx];
    v.x *= a.x; v.y *= a.y; v.z *= a.z; v.w *= a.w;
    ov[b * plane4 + idx] = v;
  }
}

extern "C" void kernel_launch(void* const* d_in, const int* in_sizes, int n_in,
                              void* d_out, int out_size) {
  const float* x       = (const float*)d_in[0];  // [8,1024,1024]
  const float* product = (const float*)d_in[1];  // [1024,128]
  const float* person  = (const float*)d_in[2];  // [1024,128]
  const float* w1      = (const float*)d_in[3];  // [256,128]
  const float* w2      = (const float*)d_in[4];  // [128,1]
  float* out = (float*)d_out;                    // [8,1024,1024]

  proj_kernel<<<dim3(P_DIM / PR_CTA_ROWS, 2), 512>>>(product, person, w1, w2);
  gemm_kernel<<<dim3(Q_DIM / TN, P_DIM / TM), 256>>>();
  mul_kernel<<<(P_DIM * Q_DIM / 4) / 256, 256>>>(x, out);
}